// round 7
// baseline (speedup 1.0000x reference)
#include <cuda_runtime.h>
#include <math.h>

#define N_USER   100000
#define N_ITEM   50000
#define N_NODES_ (N_USER + N_ITEM)   // 150000
#define NNZ_     4800000
#define EMB      64
#define N_LAYERS 3
#define BATCH_   16384
#define EPS_     1e-12f
#define NEG_SLOPE 0.2f

// ---------------- scratch (device globals: allocation-free rule) -------------
__device__ float g_ego [N_NODES_ * EMB];        // current layer input (unnormalized)
__device__ float g_side[N_NODES_ * EMB];        // A_hat @ ego (written whole by CSR spmm)
__device__ float g_all [N_NODES_ * 4 * EMB];    // concat of 4 embedding blocks
// CSR build scratch
__device__ int   g_row_cnt[N_NODES_];
__device__ int   g_row_cur[N_NODES_];           // seeded with row_off by scan
__device__ int   g_row_off[N_NODES_ + 1];
__device__ int   g_col_s  [NNZ_];
__device__ float g_val_s  [NNZ_];

// ------- init: ego = concat(user_emb, item_emb); all[:,0:64] = ego; counters=0
__global__ void init_kernel(const float* __restrict__ ue, const float* __restrict__ ie) {
    int idx = blockIdx.x * blockDim.x + threadIdx.x;      // float4 index
    const int total = N_NODES_ * EMB / 4;
    if (idx >= total) return;
    int node = idx >> 4;
    int c4   = idx & 15;
    float4 v;
    if (node < N_USER) v = __ldg((const float4*)ue + node * 16 + c4);
    else               v = __ldg((const float4*)ie + (node - N_USER) * 16 + c4);
    ((float4*)g_ego)[idx] = v;
    ((float4*)g_all)[node * 64 + c4] = v;
    if (idx < N_NODES_) g_row_cnt[idx] = 0;
}

// ---------------- CSR build: degree count ------------------------------------
__global__ void count_kernel(const int* __restrict__ rows) {
    int q = blockIdx.x * blockDim.x + threadIdx.x;
    if (q >= NNZ_ / 4) return;
    int4 r4 = __ldg((const int4*)rows + q);
    atomicAdd(&g_row_cnt[r4.x], 1);
    atomicAdd(&g_row_cnt[r4.y], 1);
    atomicAdd(&g_row_cnt[r4.z], 1);
    atomicAdd(&g_row_cnt[r4.w], 1);
}

// ---------------- CSR build: exclusive scan (single block, 1024 threads) -----
// Seeds g_row_cur with the exclusive offsets (scatter cursor trick).
__global__ void scan_kernel() {
    __shared__ int part[1024];
    const int CH = (N_NODES_ + 1023) / 1024;   // 147
    int t = threadIdx.x;
    int base = t * CH;
    int s = 0;
    for (int i = 0; i < CH; i++) {
        int idx = base + i;
        if (idx < N_NODES_) s += g_row_cnt[idx];
    }
    part[t] = s;
    __syncthreads();
    for (int off = 1; off < 1024; off <<= 1) {
        int u = (t >= off) ? part[t - off] : 0;
        __syncthreads();
        part[t] += u;
        __syncthreads();
    }
    int run = part[t] - s;          // exclusive prefix for this chunk
    for (int i = 0; i < CH; i++) {
        int idx = base + i;
        if (idx < N_NODES_) {
            g_row_off[idx] = run;
            g_row_cur[idx] = run;   // cursor starts at row start
            run += g_row_cnt[idx];
        }
    }
    if (t == 1023) g_row_off[N_NODES_] = part[1023];   // total = NNZ
}

// ---------------- CSR build: scatter edges into row-sorted arrays ------------
// 8 independent atomic->store chains per thread; position comes straight from
// the cursor atomic (no dependent row_off load/add).
__global__ void scatter_kernel(const int* __restrict__ rows,
                               const int* __restrict__ cols,
                               const float* __restrict__ vals) {
    int q = blockIdx.x * blockDim.x + threadIdx.x;   // octet id
    if (q >= NNZ_ / 8) return;
    int4 ra = __ldg((const int4*)rows + q * 2);
    int4 rb = __ldg((const int4*)rows + q * 2 + 1);
    int4 ca = __ldg((const int4*)cols + q * 2);
    int4 cb = __ldg((const int4*)cols + q * 2 + 1);
    float4 va = __ldg((const float4*)vals + q * 2);
    float4 vb = __ldg((const float4*)vals + q * 2 + 1);
    int   r[8] = {ra.x, ra.y, ra.z, ra.w, rb.x, rb.y, rb.z, rb.w};
    int   c[8] = {ca.x, ca.y, ca.z, ca.w, cb.x, cb.y, cb.z, cb.w};
    float v[8] = {va.x, va.y, va.z, va.w, vb.x, vb.y, vb.z, vb.w};
    int p[8];
#pragma unroll
    for (int u = 0; u < 8; u++) p[u] = atomicAdd(&g_row_cur[r[u]], 1);
#pragma unroll
    for (int u = 0; u < 8; u++) g_col_s[p[u]] = c[u];
#pragma unroll
    for (int u = 0; u < 8; u++) g_val_s[p[u]] = v[u];
}

// ---------------- CSR SpMM (exact R5-measured version) ------------------------
// 16 lanes per row; register float4 accumulator; 4-edge unroll for MLP.
__global__ void spmm_csr_kernel() {
    int t = blockIdx.x * blockDim.x + threadIdx.x;
    int r = t >> 4;                 // row id (grid sized exactly)
    int l = t & 15;
    int beg = __ldg(&g_row_off[r]);
    int end = __ldg(&g_row_off[r + 1]);
    float4 acc = make_float4(0.f, 0.f, 0.f, 0.f);
    int e = beg;
    for (; e + 4 <= end; e += 4) {
        int   c0 = __ldg(&g_col_s[e + 0]);
        int   c1 = __ldg(&g_col_s[e + 1]);
        int   c2 = __ldg(&g_col_s[e + 2]);
        int   c3 = __ldg(&g_col_s[e + 3]);
        float v0 = __ldg(&g_val_s[e + 0]);
        float v1 = __ldg(&g_val_s[e + 1]);
        float v2 = __ldg(&g_val_s[e + 2]);
        float v3 = __ldg(&g_val_s[e + 3]);
        float4 g0 = __ldg((const float4*)g_ego + c0 * 16 + l);
        float4 g1 = __ldg((const float4*)g_ego + c1 * 16 + l);
        float4 g2 = __ldg((const float4*)g_ego + c2 * 16 + l);
        float4 g3 = __ldg((const float4*)g_ego + c3 * 16 + l);
        acc.x += g0.x * v0 + g1.x * v1 + g2.x * v2 + g3.x * v3;
        acc.y += g0.y * v0 + g1.y * v1 + g2.y * v2 + g3.y * v3;
        acc.z += g0.z * v0 + g1.z * v1 + g2.z * v2 + g3.z * v3;
        acc.w += g0.w * v0 + g1.w * v1 + g2.w * v2 + g3.w * v3;
    }
    for (; e < end; e++) {
        int   c = __ldg(&g_col_s[e]);
        float v = __ldg(&g_val_s[e]);
        float4 g = __ldg((const float4*)g_ego + c * 16 + l);
        acc.x += g.x * v; acc.y += g.y * v; acc.z += g.z * v; acc.w += g.w * v;
    }
    ((float4*)g_side)[r * 16 + l] = acc;
}

// ---------------- fused dense transform + leaky_relu + L2-normalize ----------
// R1-measured structure (92us): 64-row tile, 256 threads, thread(ty,tx)
// computes rows ty*4..+3, cols tx*4..+3.
__global__ void transform_kernel(const float* __restrict__ Wgc,
                                 const float* __restrict__ bgc,
                                 const float* __restrict__ Wbi,
                                 const float* __restrict__ bbi,
                                 int layer) {
    extern __shared__ float sh[];
    float* Ssh = sh;                    // [64][65]
    float* Psh = Ssh + 64 * 65;         // [64][65]
    float* Wg  = Psh + 64 * 65;         // [64][64]
    float* Wb  = Wg  + 64 * 64;         // [64][64]
    float* bs  = Wb  + 64 * 64;         // [64]

    const int tid = threadIdx.x;
    const int rowBase = blockIdx.x * 64;

    for (int i = tid; i < 1024; i += 256) {
        ((float4*)Wg)[i] = __ldg((const float4*)Wgc + i);
        ((float4*)Wb)[i] = __ldg((const float4*)Wbi + i);
    }
    if (tid < 64) bs[tid] = __ldg(bgc + tid) + __ldg(bbi + tid);

    for (int i = tid; i < 1024; i += 256) {
        int r  = i >> 4;
        int c4 = i & 15;
        int gr = rowBase + r;
        float4 s = make_float4(0.f, 0.f, 0.f, 0.f);
        float4 e = make_float4(0.f, 0.f, 0.f, 0.f);
        if (gr < N_NODES_) {
            s = ((const float4*)g_side)[gr * 16 + c4];
            e = ((const float4*)g_ego )[gr * 16 + c4];
        }
        float* sp = Ssh + r * 65 + c4 * 4;
        sp[0] = s.x; sp[1] = s.y; sp[2] = s.z; sp[3] = s.w;
        float* pp = Psh + r * 65 + c4 * 4;
        pp[0] = e.x * s.x; pp[1] = e.y * s.y; pp[2] = e.z * s.z; pp[3] = e.w * s.w;
    }
    __syncthreads();

    const int tx = tid & 15;
    const int ty = tid >> 4;
    float acc[4][4];
#pragma unroll
    for (int i = 0; i < 4; i++)
#pragma unroll
        for (int j = 0; j < 4; j++) acc[i][j] = 0.f;

#pragma unroll 8
    for (int k = 0; k < 64; k++) {
        float4 bg = *(const float4*)&Wg[k * 64 + tx * 4];
        float4 bb = *(const float4*)&Wb[k * 64 + tx * 4];
        float as[4], ap[4];
#pragma unroll
        for (int i = 0; i < 4; i++) {
            as[i] = Ssh[(ty * 4 + i) * 65 + k];
            ap[i] = Psh[(ty * 4 + i) * 65 + k];
        }
#pragma unroll
        for (int i = 0; i < 4; i++) {
            acc[i][0] += as[i] * bg.x + ap[i] * bb.x;
            acc[i][1] += as[i] * bg.y + ap[i] * bb.y;
            acc[i][2] += as[i] * bg.z + ap[i] * bb.z;
            acc[i][3] += as[i] * bg.w + ap[i] * bb.w;
        }
    }

    const int colBase = tx * 4;
    float v[4][4];
    float sq[4];
#pragma unroll
    for (int i = 0; i < 4; i++) {
        float x0 = acc[i][0] + bs[colBase + 0];
        float x1 = acc[i][1] + bs[colBase + 1];
        float x2 = acc[i][2] + bs[colBase + 2];
        float x3 = acc[i][3] + bs[colBase + 3];
        x0 = fmaxf(x0, NEG_SLOPE * x0);
        x1 = fmaxf(x1, NEG_SLOPE * x1);
        x2 = fmaxf(x2, NEG_SLOPE * x2);
        x3 = fmaxf(x3, NEG_SLOPE * x3);
        v[i][0] = x0; v[i][1] = x1; v[i][2] = x2; v[i][3] = x3;
        float s = x0 * x0 + x1 * x1 + x2 * x2 + x3 * x3;
#pragma unroll
        for (int off = 1; off < 16; off <<= 1)
            s += __shfl_xor_sync(0xffffffffu, s, off);
        sq[i] = s;
    }

#pragma unroll
    for (int i = 0; i < 4; i++) {
        int gr = rowBase + ty * 4 + i;
        if (gr >= N_NODES_) continue;
        float inv = 1.0f / fmaxf(sqrtf(sq[i]), EPS_);
        float4 raw = make_float4(v[i][0], v[i][1], v[i][2], v[i][3]);
        float4 nrm = make_float4(v[i][0] * inv, v[i][1] * inv, v[i][2] * inv, v[i][3] * inv);
        *(float4*)&g_ego[(size_t)gr * EMB + colBase] = raw;
        *(float4*)&g_all[(size_t)gr * 256 + (layer + 1) * 64 + colBase] = nrm;
    }
}

// ---------------- GMF head: sigmoid((u*i)@W_out + b_out) ---------------------
__global__ void head_kernel(const int* __restrict__ uidx,
                            const int* __restrict__ iidx,
                            const float* __restrict__ Wout,
                            const float* __restrict__ bout,
                            float* __restrict__ out) {
    int gw = (blockIdx.x * blockDim.x + threadIdx.x) >> 5;
    if (gw >= BATCH_) return;
    int lane = threadIdx.x & 31;
    int u  = __ldg(&uidx[gw]);
    int it = __ldg(&iidx[gw]) + N_USER;
    const float4* ur = (const float4*)(g_all + (size_t)u  * 256);
    const float4* ir = (const float4*)(g_all + (size_t)it * 256);
    const float4* w4 = (const float4*)Wout;
    float acc = 0.f;
#pragma unroll
    for (int q = 0; q < 2; q++) {
        int c = lane + q * 32;
        float4 a = ur[c];
        float4 b = ir[c];
        float4 w = __ldg(&w4[c]);
        acc += a.x * b.x * w.x + a.y * b.y * w.y + a.z * b.z * w.z + a.w * b.w * w.w;
    }
#pragma unroll
    for (int off = 16; off; off >>= 1)
        acc += __shfl_xor_sync(0xffffffffu, acc, off);
    if (lane == 0) {
        float z = acc + __ldg(bout);
        out[gw] = 1.0f / (1.0f + expf(-z));
    }
}

// ---------------- launch ------------------------------------------------------
extern "C" void kernel_launch(void* const* d_in, const int* in_sizes, int n_in,
                              void* d_out, int out_size) {
    const int*   user_idx = (const int*)  d_in[0];
    const int*   item_idx = (const int*)  d_in[1];
    const int*   adj_rows = (const int*)  d_in[2];
    const int*   adj_cols = (const int*)  d_in[3];
    const float* adj_vals = (const float*)d_in[4];
    const float* user_emb = (const float*)d_in[5];
    const float* item_emb = (const float*)d_in[6];
    const float* W_gc     = (const float*)d_in[7];
    const float* b_gc     = (const float*)d_in[8];
    const float* W_bi     = (const float*)d_in[9];
    const float* b_bi     = (const float*)d_in[10];
    const float* W_out    = (const float*)d_in[11];
    const float* b_out    = (const float*)d_in[12];
    float* out = (float*)d_out;

    const int smem = (64 * 65 * 2 + 64 * 64 * 2 + 64) * (int)sizeof(float);  // 66304 B
    cudaFuncSetAttribute(transform_kernel,
                         cudaFuncAttributeMaxDynamicSharedMemorySize, smem);

    const int vec_blocks = (N_NODES_ * EMB / 4) / 256;   // 9375 exactly
    init_kernel<<<vec_blocks, 256>>>(user_emb, item_emb);

    count_kernel<<<(NNZ_ / 4 + 255) / 256, 256>>>(adj_rows);
    scan_kernel<<<1, 1024>>>();
    scatter_kernel<<<(NNZ_ / 8 + 255) / 256, 256>>>(adj_rows, adj_cols, adj_vals);

    const int spmm_blocks = (N_NODES_ * 16) / 256;       // 9375 exactly
    const int tile_blocks = (N_NODES_ + 63) / 64;        // 2344

    for (int l = 0; l < N_LAYERS; l++) {
        spmm_csr_kernel<<<spmm_blocks, 256>>>();
        transform_kernel<<<tile_blocks, 256, smem>>>(W_gc + l * EMB * EMB,
                                                     b_gc + l * EMB,
                                                     W_bi + l * EMB * EMB,
                                                     b_bi + l * EMB,
                                                     l);
    }

    head_kernel<<<(BATCH_ * 32) / 256, 256>>>(user_idx, item_idx, W_out, b_out, out);
}

// round 8
// speedup vs baseline: 1.1567x; 1.1567x over previous
#include <cuda_runtime.h>
#include <cuda_fp16.h>
#include <math.h>

#define N_USER   100000
#define N_ITEM   50000
#define N_NODES_ (N_USER + N_ITEM)   // 150000
#define NNZ_     4800000
#define EMB      64
#define N_LAYERS 3
#define BATCH_   16384
#define EPS_     1e-12f
#define NEG_SLOPE 0.2f

// ---------------- scratch (device globals: allocation-free rule) -------------
__device__ float  g_ego  [N_NODES_ * EMB];      // fp32 layer input (unnormalized)
__device__ __half g_ego_h[N_NODES_ * EMB];      // fp16 shadow for spmm gathers
__device__ float  g_side [N_NODES_ * EMB];      // A_hat @ ego (written whole by CSR spmm)
__device__ float  g_all  [N_NODES_ * 4 * EMB];  // concat of 4 embedding blocks
// CSR build scratch
__device__ int   g_row_cnt[N_NODES_];
__device__ int   g_row_cur[N_NODES_];
__device__ int   g_row_off[N_NODES_ + 1];
__device__ int   g_col_s  [NNZ_];
__device__ float g_val_s  [NNZ_];

// ------- init: ego = concat(user_emb, item_emb) (fp32 + fp16 shadow) ---------
__global__ void init_kernel(const float* __restrict__ ue, const float* __restrict__ ie) {
    int idx = blockIdx.x * blockDim.x + threadIdx.x;      // float4 / half4 index
    const int total = N_NODES_ * EMB / 4;
    if (idx >= total) return;
    int node = idx >> 4;
    int c4   = idx & 15;
    float4 v;
    if (node < N_USER) v = __ldg((const float4*)ue + node * 16 + c4);
    else               v = __ldg((const float4*)ie + (node - N_USER) * 16 + c4);
    ((float4*)g_ego)[idx] = v;
    ((float4*)g_all)[node * 64 + c4] = v;
    __half2 h0 = __floats2half2_rn(v.x, v.y);
    __half2 h1 = __floats2half2_rn(v.z, v.w);
    uint2 pk;
    pk.x = *(unsigned*)&h0;
    pk.y = *(unsigned*)&h1;
    ((uint2*)g_ego_h)[idx] = pk;
    if (idx < N_NODES_) { g_row_cnt[idx] = 0; g_row_cur[idx] = 0; }
}

// ---------------- CSR build: degree count ------------------------------------
__global__ void count_kernel(const int* __restrict__ rows) {
    int q = blockIdx.x * blockDim.x + threadIdx.x;
    if (q >= NNZ_ / 4) return;
    int4 r4 = __ldg((const int4*)rows + q);
    atomicAdd(&g_row_cnt[r4.x], 1);
    atomicAdd(&g_row_cnt[r4.y], 1);
    atomicAdd(&g_row_cnt[r4.z], 1);
    atomicAdd(&g_row_cnt[r4.w], 1);
}

// ---------------- CSR build: exclusive scan (single block, 1024 threads) -----
__global__ void scan_kernel() {
    __shared__ int part[1024];
    const int CH = (N_NODES_ + 1023) / 1024;   // 147
    int t = threadIdx.x;
    int base = t * CH;
    int s = 0;
    for (int i = 0; i < CH; i++) {
        int idx = base + i;
        if (idx < N_NODES_) s += g_row_cnt[idx];
    }
    part[t] = s;
    __syncthreads();
    for (int off = 1; off < 1024; off <<= 1) {
        int u = (t >= off) ? part[t - off] : 0;
        __syncthreads();
        part[t] += u;
        __syncthreads();
    }
    int run = part[t] - s;          // exclusive prefix for this chunk
    for (int i = 0; i < CH; i++) {
        int idx = base + i;
        if (idx < N_NODES_) {
            g_row_off[idx] = run;
            run += g_row_cnt[idx];
        }
    }
    if (t == 1023) g_row_off[N_NODES_] = part[1023];   // total = NNZ
}

// ---------------- CSR build: scatter edges (exact R5-measured version) --------
__global__ void scatter_kernel(const int* __restrict__ rows,
                               const int* __restrict__ cols,
                               const float* __restrict__ vals) {
    int q = blockIdx.x * blockDim.x + threadIdx.x;
    if (q >= NNZ_ / 4) return;
    int4   r4 = __ldg((const int4*)  rows + q);
    int4   c4 = __ldg((const int4*)  cols + q);
    float4 v4 = __ldg((const float4*)vals + q);
    int p;
    p = __ldg(&g_row_off[r4.x]) + atomicAdd(&g_row_cur[r4.x], 1);
    g_col_s[p] = c4.x; g_val_s[p] = v4.x;
    p = __ldg(&g_row_off[r4.y]) + atomicAdd(&g_row_cur[r4.y], 1);
    g_col_s[p] = c4.y; g_val_s[p] = v4.y;
    p = __ldg(&g_row_off[r4.z]) + atomicAdd(&g_row_cur[r4.z], 1);
    g_col_s[p] = c4.z; g_val_s[p] = v4.z;
    p = __ldg(&g_row_off[r4.w]) + atomicAdd(&g_row_cur[r4.w], 1);
    g_col_s[p] = c4.w; g_val_s[p] = v4.w;
}

// ---------------- CSR SpMM: fp16 gather, fp32 accumulate ----------------------
// 16 lanes per row; 8 B (4 halves) per lane per edge; 4-edge unroll (MLP=4).
__global__ void spmm_csr_kernel() {
    int t = blockIdx.x * blockDim.x + threadIdx.x;
    int r = t >> 4;                 // row id (grid sized exactly)
    int l = t & 15;
    int beg = __ldg(&g_row_off[r]);
    int end = __ldg(&g_row_off[r + 1]);
    float4 acc = make_float4(0.f, 0.f, 0.f, 0.f);
    int e = beg;
    for (; e + 4 <= end; e += 4) {
        int   c0 = __ldg(&g_col_s[e + 0]);
        int   c1 = __ldg(&g_col_s[e + 1]);
        int   c2 = __ldg(&g_col_s[e + 2]);
        int   c3 = __ldg(&g_col_s[e + 3]);
        float v0 = __ldg(&g_val_s[e + 0]);
        float v1 = __ldg(&g_val_s[e + 1]);
        float v2 = __ldg(&g_val_s[e + 2]);
        float v3 = __ldg(&g_val_s[e + 3]);
        uint2 w0 = __ldg((const uint2*)g_ego_h + c0 * 16 + l);
        uint2 w1 = __ldg((const uint2*)g_ego_h + c1 * 16 + l);
        uint2 w2 = __ldg((const uint2*)g_ego_h + c2 * 16 + l);
        uint2 w3 = __ldg((const uint2*)g_ego_h + c3 * 16 + l);
        float2 a0 = __half22float2(*(const __half2*)&w0.x);
        float2 b0 = __half22float2(*(const __half2*)&w0.y);
        float2 a1 = __half22float2(*(const __half2*)&w1.x);
        float2 b1 = __half22float2(*(const __half2*)&w1.y);
        float2 a2 = __half22float2(*(const __half2*)&w2.x);
        float2 b2 = __half22float2(*(const __half2*)&w2.y);
        float2 a3 = __half22float2(*(const __half2*)&w3.x);
        float2 b3 = __half22float2(*(const __half2*)&w3.y);
        acc.x += a0.x * v0 + a1.x * v1 + a2.x * v2 + a3.x * v3;
        acc.y += a0.y * v0 + a1.y * v1 + a2.y * v2 + a3.y * v3;
        acc.z += b0.x * v0 + b1.x * v1 + b2.x * v2 + b3.x * v3;
        acc.w += b0.y * v0 + b1.y * v1 + b2.y * v2 + b3.y * v3;
    }
    for (; e < end; e++) {
        int   c = __ldg(&g_col_s[e]);
        float v = __ldg(&g_val_s[e]);
        uint2 w = __ldg((const uint2*)g_ego_h + c * 16 + l);
        float2 a = __half22float2(*(const __half2*)&w.x);
        float2 b = __half22float2(*(const __half2*)&w.y);
        acc.x += a.x * v; acc.y += a.y * v; acc.z += b.x * v; acc.w += b.y * v;
    }
    ((float4*)g_side)[r * 16 + l] = acc;
}

// ---------------- fused dense transform + leaky_relu + L2-normalize ----------
// R1-measured structure (92us). Epilogue additionally refreshes the fp16
// shadow of ego for the next layer's spmm (layers 0,1 only).
__global__ void transform_kernel(const float* __restrict__ Wgc,
                                 const float* __restrict__ bgc,
                                 const float* __restrict__ Wbi,
                                 const float* __restrict__ bbi,
                                 int layer) {
    extern __shared__ float sh[];
    float* Ssh = sh;                    // [64][65]
    float* Psh = Ssh + 64 * 65;         // [64][65]
    float* Wg  = Psh + 64 * 65;         // [64][64]
    float* Wb  = Wg  + 64 * 64;         // [64][64]
    float* bs  = Wb  + 64 * 64;         // [64]

    const int tid = threadIdx.x;
    const int rowBase = blockIdx.x * 64;

    for (int i = tid; i < 1024; i += 256) {
        ((float4*)Wg)[i] = __ldg((const float4*)Wgc + i);
        ((float4*)Wb)[i] = __ldg((const float4*)Wbi + i);
    }
    if (tid < 64) bs[tid] = __ldg(bgc + tid) + __ldg(bbi + tid);

    for (int i = tid; i < 1024; i += 256) {
        int r  = i >> 4;
        int c4 = i & 15;
        int gr = rowBase + r;
        float4 s = make_float4(0.f, 0.f, 0.f, 0.f);
        float4 e = make_float4(0.f, 0.f, 0.f, 0.f);
        if (gr < N_NODES_) {
            s = ((const float4*)g_side)[gr * 16 + c4];
            e = ((const float4*)g_ego )[gr * 16 + c4];
        }
        float* sp = Ssh + r * 65 + c4 * 4;
        sp[0] = s.x; sp[1] = s.y; sp[2] = s.z; sp[3] = s.w;
        float* pp = Psh + r * 65 + c4 * 4;
        pp[0] = e.x * s.x; pp[1] = e.y * s.y; pp[2] = e.z * s.z; pp[3] = e.w * s.w;
    }
    __syncthreads();

    const int tx = tid & 15;
    const int ty = tid >> 4;
    float acc[4][4];
#pragma unroll
    for (int i = 0; i < 4; i++)
#pragma unroll
        for (int j = 0; j < 4; j++) acc[i][j] = 0.f;

#pragma unroll 8
    for (int k = 0; k < 64; k++) {
        float4 bg = *(const float4*)&Wg[k * 64 + tx * 4];
        float4 bb = *(const float4*)&Wb[k * 64 + tx * 4];
        float as[4], ap[4];
#pragma unroll
        for (int i = 0; i < 4; i++) {
            as[i] = Ssh[(ty * 4 + i) * 65 + k];
            ap[i] = Psh[(ty * 4 + i) * 65 + k];
        }
#pragma unroll
        for (int i = 0; i < 4; i++) {
            acc[i][0] += as[i] * bg.x + ap[i] * bb.x;
            acc[i][1] += as[i] * bg.y + ap[i] * bb.y;
            acc[i][2] += as[i] * bg.z + ap[i] * bb.z;
            acc[i][3] += as[i] * bg.w + ap[i] * bb.w;
        }
    }

    const int colBase = tx * 4;
    float v[4][4];
    float sq[4];
#pragma unroll
    for (int i = 0; i < 4; i++) {
        float x0 = acc[i][0] + bs[colBase + 0];
        float x1 = acc[i][1] + bs[colBase + 1];
        float x2 = acc[i][2] + bs[colBase + 2];
        float x3 = acc[i][3] + bs[colBase + 3];
        x0 = fmaxf(x0, NEG_SLOPE * x0);
        x1 = fmaxf(x1, NEG_SLOPE * x1);
        x2 = fmaxf(x2, NEG_SLOPE * x2);
        x3 = fmaxf(x3, NEG_SLOPE * x3);
        v[i][0] = x0; v[i][1] = x1; v[i][2] = x2; v[i][3] = x3;
        float s = x0 * x0 + x1 * x1 + x2 * x2 + x3 * x3;
#pragma unroll
        for (int off = 1; off < 16; off <<= 1)
            s += __shfl_xor_sync(0xffffffffu, s, off);
        sq[i] = s;
    }

#pragma unroll
    for (int i = 0; i < 4; i++) {
        int gr = rowBase + ty * 4 + i;
        if (gr >= N_NODES_) continue;
        float inv = 1.0f / fmaxf(sqrtf(sq[i]), EPS_);
        float4 raw = make_float4(v[i][0], v[i][1], v[i][2], v[i][3]);
        float4 nrm = make_float4(v[i][0] * inv, v[i][1] * inv, v[i][2] * inv, v[i][3] * inv);
        *(float4*)&g_ego[(size_t)gr * EMB + colBase] = raw;
        *(float4*)&g_all[(size_t)gr * 256 + (layer + 1) * 64 + colBase] = nrm;
        if (layer < N_LAYERS - 1) {
            __half2 h0 = __floats2half2_rn(raw.x, raw.y);
            __half2 h1 = __floats2half2_rn(raw.z, raw.w);
            uint2 pk;
            pk.x = *(unsigned*)&h0;
            pk.y = *(unsigned*)&h1;
            *(uint2*)&g_ego_h[(size_t)gr * EMB + colBase] = pk;
        }
    }
}

// ---------------- GMF head: sigmoid((u*i)@W_out + b_out) ---------------------
__global__ void head_kernel(const int* __restrict__ uidx,
                            const int* __restrict__ iidx,
                            const float* __restrict__ Wout,
                            const float* __restrict__ bout,
                            float* __restrict__ out) {
    int gw = (blockIdx.x * blockDim.x + threadIdx.x) >> 5;
    if (gw >= BATCH_) return;
    int lane = threadIdx.x & 31;
    int u  = __ldg(&uidx[gw]);
    int it = __ldg(&iidx[gw]) + N_USER;
    const float4* ur = (const float4*)(g_all + (size_t)u  * 256);
    const float4* ir = (const float4*)(g_all + (size_t)it * 256);
    const float4* w4 = (const float4*)Wout;
    float acc = 0.f;
#pragma unroll
    for (int q = 0; q < 2; q++) {
        int c = lane + q * 32;
        float4 a = ur[c];
        float4 b = ir[c];
        float4 w = __ldg(&w4[c]);
        acc += a.x * b.x * w.x + a.y * b.y * w.y + a.z * b.z * w.z + a.w * b.w * w.w;
    }
#pragma unroll
    for (int off = 16; off; off >>= 1)
        acc += __shfl_xor_sync(0xffffffffu, acc, off);
    if (lane == 0) {
        float z = acc + __ldg(bout);
        out[gw] = 1.0f / (1.0f + expf(-z));
    }
}

// ---------------- launch ------------------------------------------------------
extern "C" void kernel_launch(void* const* d_in, const int* in_sizes, int n_in,
                              void* d_out, int out_size) {
    const int*   user_idx = (const int*)  d_in[0];
    const int*   item_idx = (const int*)  d_in[1];
    const int*   adj_rows = (const int*)  d_in[2];
    const int*   adj_cols = (const int*)  d_in[3];
    const float* adj_vals = (const float*)d_in[4];
    const float* user_emb = (const float*)d_in[5];
    const float* item_emb = (const float*)d_in[6];
    const float* W_gc     = (const float*)d_in[7];
    const float* b_gc     = (const float*)d_in[8];
    const float* W_bi     = (const float*)d_in[9];
    const float* b_bi     = (const float*)d_in[10];
    const float* W_out    = (const float*)d_in[11];
    const float* b_out    = (const float*)d_in[12];
    float* out = (float*)d_out;

    const int smem = (64 * 65 * 2 + 64 * 64 * 2 + 64) * (int)sizeof(float);  // 66304 B
    cudaFuncSetAttribute(transform_kernel,
                         cudaFuncAttributeMaxDynamicSharedMemorySize, smem);

    const int vec_blocks = (N_NODES_ * EMB / 4) / 256;   // 9375 exactly
    init_kernel<<<vec_blocks, 256>>>(user_emb, item_emb);

    count_kernel<<<(NNZ_ / 4 + 255) / 256, 256>>>(adj_rows);
    scan_kernel<<<1, 1024>>>();
    scatter_kernel<<<(NNZ_ / 4 + 255) / 256, 256>>>(adj_rows, adj_cols, adj_vals);

    const int spmm_blocks = (N_NODES_ * 16) / 256;       // 9375 exactly
    const int tile_blocks = (N_NODES_ + 63) / 64;        // 2344

    for (int l = 0; l < N_LAYERS; l++) {
        spmm_csr_kernel<<<spmm_blocks, 256>>>();
        transform_kernel<<<tile_blocks, 256, smem>>>(W_gc + l * EMB * EMB,
                                                     b_gc + l * EMB,
                                                     W_bi + l * EMB * EMB,
                                                     b_bi + l * EMB,
                                                     l);
    }

    head_kernel<<<(BATCH_ * 32) / 256, 256>>>(user_idx, item_idx, W_out, b_out, out);
}